// round 15
// baseline (speedup 1.0000x reference)
#include <cuda_runtime.h>
#include <cuda_fp16.h>
#include <float.h>
#include <stdint.h>

// Problem constants (fixed shapes)
#define NN 50000
#define NE 800000
#define INF_ 512
#define HID 256
#define NH 8
#define HD 32
#define NCLS 40
#define NEG_SLOPE 0.2f

// ---------------- scratch (device globals; no allocs allowed) ----------------
__device__ __align__(16) __half g_feath[NN * HID];
__device__ __align__(16) __half g_hh[NN * HID];
__device__ __align__(16) float g_feat2[NN * NCLS];
__device__ __align__(16) float g_el[NN * NH];
__device__ __align__(16) float g_er[NN * NH];
__device__ __align__(16) float g_el2[NN];
__device__ __align__(16) float g_er2[NN];
__device__ __align__(16) __half g_a0h[NN * INF_];
__device__ __align__(16) __half g_w0h[INF_ * HID];
__device__ __align__(16) __half g_w1h[HID * HID];
__device__ __align__(16) __half g_w2h[HID * NCLS];
__device__ int g_deg[NN];
__device__ int g_cursor[NN];
__device__ int g_rowptr[NN + 1];
__device__ int g_esrc[NE];

// ---------------- bit casts ----------------
__device__ __forceinline__ uint32_t h2_to_u32(half2 h) {
    uint32_t u;
    memcpy(&u, &h, 4);
    return u;
}
__device__ __forceinline__ half2 u32_to_h2(uint32_t u) {
    half2 h;
    memcpy(&h, &u, 4);
    return h;
}

// ---------------- CSR build ----------------
__global__ void k_zero(int* p, int n) {
    int i = blockIdx.x * blockDim.x + threadIdx.x;
    if (i < n) p[i] = 0;
}

__global__ void k_hist(const int* __restrict__ dst, int* deg, int E) {
    int i = blockIdx.x * blockDim.x + threadIdx.x;
    if (i < E) atomicAdd(&deg[dst[i]], 1);
}

__global__ void k_scan(const int* __restrict__ deg, int* __restrict__ rowptr,
                       int* __restrict__ cursor, int n) {
    __shared__ int wsum[32];
    __shared__ int carry;
    int t = threadIdx.x, lane = t & 31, wid = t >> 5;
    if (t == 0) carry = 0;
    __syncthreads();
    for (int base = 0; base < n; base += blockDim.x) {
        int i = base + t;
        int v = (i < n) ? deg[i] : 0;
        int x = v;
#pragma unroll
        for (int o = 1; o < 32; o <<= 1) {
            int y = __shfl_up_sync(0xffffffffu, x, o);
            if (lane >= o) x += y;
        }
        if (lane == 31) wsum[wid] = x;
        __syncthreads();
        if (wid == 0) {
            int s = (lane < (int)(blockDim.x >> 5)) ? wsum[lane] : 0;
#pragma unroll
            for (int o = 1; o < 32; o <<= 1) {
                int y = __shfl_up_sync(0xffffffffu, s, o);
                if (lane >= o) s += y;
            }
            wsum[lane] = s;
        }
        __syncthreads();
        int woff = (wid == 0) ? 0 : wsum[wid - 1];
        int excl = carry + woff + x - v;
        if (i < n) { rowptr[i] = excl; cursor[i] = excl; }
        int total = wsum[(blockDim.x >> 5) - 1];
        __syncthreads();
        if (t == 0) carry += total;
        __syncthreads();
    }
    if (threadIdx.x == 0) rowptr[n] = carry;
}

__global__ void k_scatter(const int* __restrict__ dst, const int* __restrict__ src,
                          int* cursor, int* __restrict__ esrc, int E) {
    int i = blockIdx.x * blockDim.x + threadIdx.x;
    if (i < E) {
        int p = atomicAdd(&cursor[dst[i]], 1);
        esrc[p] = src[i];
    }
}

// ---------------- fp32 -> fp16 convert (8 elems/thread) ----------------
__global__ void k_cvth(__half* __restrict__ dst, const float* __restrict__ src, int n8) {
    int i = blockIdx.x * blockDim.x + threadIdx.x;
    if (i >= n8) return;
    float4 v0 = ((const float4*)src)[i * 2];
    float4 v1 = ((const float4*)src)[i * 2 + 1];
    uint4 pk;
    pk.x = h2_to_u32(__floats2half2_rn(v0.x, v0.y));
    pk.y = h2_to_u32(__floats2half2_rn(v0.z, v0.w));
    pk.z = h2_to_u32(__floats2half2_rn(v1.x, v1.y));
    pk.w = h2_to_u32(__floats2half2_rn(v1.z, v1.w));
    ((uint4*)dst)[i] = pk;
}

// ---------------- FP16 tensor-core GEMM core ----------------
#define BM 128
#define BN 128
#define BK 32
#define NSTAGE 4
#define ASTR 40
#define BSTR 136
#define A_ST_H (BM * ASTR)
#define B_ST_H (BK * BSTR)
#define SMEM_BYTES (NSTAGE * (A_ST_H + B_ST_H) * 2)

__device__ __forceinline__ void ldsm4(uint32_t* r, uint32_t addr) {
    asm volatile("ldmatrix.sync.aligned.m8n8.x4.shared.b16 {%0,%1,%2,%3}, [%4];"
                 : "=r"(r[0]), "=r"(r[1]), "=r"(r[2]), "=r"(r[3]) : "r"(addr));
}
__device__ __forceinline__ void ldsm4t(uint32_t* r, uint32_t addr) {
    asm volatile("ldmatrix.sync.aligned.m8n8.x4.trans.shared.b16 {%0,%1,%2,%3}, [%4];"
                 : "=r"(r[0]), "=r"(r[1]), "=r"(r[2]), "=r"(r[3]) : "r"(addr));
}
__device__ __forceinline__ void mma16(float* c, const uint32_t* a, const uint32_t* b) {
    asm volatile(
        "mma.sync.aligned.m16n8k16.row.col.f32.f16.f16.f32 "
        "{%0,%1,%2,%3}, {%4,%5,%6,%7}, {%8,%9}, {%0,%1,%2,%3};"
        : "+f"(c[0]), "+f"(c[1]), "+f"(c[2]), "+f"(c[3])
        : "r"(a[0]), "r"(a[1]), "r"(a[2]), "r"(a[3]), "r"(b[0]), "r"(b[1]));
}
__device__ __forceinline__ void cp16(uint32_t dst, const void* src, bool pred) {
    int sz = pred ? 16 : 0;
    asm volatile("cp.async.cg.shared.global [%0], [%1], 16, %2;"
                 :: "r"(dst), "l"(src), "r"(sz));
}
__device__ __forceinline__ void cp_commit() {
    asm volatile("cp.async.commit_group;");
}
template <int N>
__device__ __forceinline__ void cp_wait() {
    asm volatile("cp.async.wait_group %0;" :: "n"(N));
}

template <int OUT_HALF, int DO_ELR>
__device__ __forceinline__ void mma_body(const __half* __restrict__ A,
                                         const __half* __restrict__ B,
                                         void* __restrict__ Cv,
                                         int M, int N, int K,
                                         const float* __restrict__ al,
                                         const float* __restrict__ ar,
                                         float* __restrict__ el,
                                         float* __restrict__ er) {
    extern __shared__ __half smemh[];
    uint32_t sbase;
    asm("{ .reg .u64 t; cvta.to.shared.u64 t, %1; cvt.u32.u64 %0, t; }"
        : "=r"(sbase) : "l"(smemh));

    int tid = threadIdx.x;
    int warp = tid >> 5, lane = tid & 31;
    int gid = lane >> 2, tg = lane & 3;
    int wm = warp >> 2, wn = warp & 3;
    int m0 = blockIdx.x * BM, n0 = blockIdx.y * BN;

    int ar_ = tid >> 2;
    int ac = (tid & 3) * 8;
    int bk = tid >> 4;
    int bn = (tid & 15) * 8;
    bool bok = (n0 + bn + 8 <= N);

    float acc[4][4][4];
#pragma unroll
    for (int mi = 0; mi < 4; mi++)
#pragma unroll
        for (int ni = 0; ni < 4; ni++)
#pragma unroll
            for (int r = 0; r < 4; r++) acc[mi][ni][r] = 0.f;

    int kTiles = K / BK;

#define FILL_STAGE_H(s, kt)                                                            \
    do {                                                                               \
        int k0 = (kt) * BK;                                                            \
        uint32_t abase = sbase + (uint32_t)(s) * (A_ST_H * 2);                         \
        uint32_t bbase = sbase + (uint32_t)(NSTAGE * A_ST_H + (s) * B_ST_H) * 2;       \
        cp16(abase + (ar_ * ASTR + ac) * 2,                                            \
             A + (size_t)(m0 + ar_) * K + k0 + ac, m0 + ar_ < M);                      \
        cp16(abase + ((ar_ + 64) * ASTR + ac) * 2,                                     \
             A + (size_t)(m0 + ar_ + 64) * K + k0 + ac, m0 + ar_ + 64 < M);            \
        cp16(bbase + (bk * BSTR + bn) * 2,                                             \
             B + (size_t)(k0 + bk) * N + n0 + bn, bok);                                \
        cp16(bbase + ((bk + 16) * BSTR + bn) * 2,                                      \
             B + (size_t)(k0 + bk + 16) * N + n0 + bn, bok);                           \
    } while (0)

#pragma unroll
    for (int s = 0; s < NSTAGE - 1; s++) {
        if (s < kTiles) FILL_STAGE_H(s, s);
        cp_commit();
    }

    int lrow = lane & 7, lg = lane >> 3;

    for (int kt = 0; kt < kTiles; kt++) {
        cp_wait<NSTAGE - 2>();
        __syncthreads();

        int nkt = kt + NSTAGE - 1;
        if (nkt < kTiles) FILL_STAGE_H(nkt % NSTAGE, nkt);
        cp_commit();

        int buf = kt % NSTAGE;
        uint32_t abase = sbase + (uint32_t)buf * (A_ST_H * 2);
        uint32_t bbase = sbase + (uint32_t)(NSTAGE * A_ST_H + buf * B_ST_H) * 2;

#pragma unroll
        for (int kstep = 0; kstep < 2; kstep++) {
            uint32_t af[4][4], bf[4][2];
            int colA = kstep * 16 + (lg >> 1) * 8;
#pragma unroll
            for (int mi = 0; mi < 4; mi++) {
                int row = wm * 64 + mi * 16 + (lg & 1) * 8 + lrow;
                ldsm4(af[mi], abase + (uint32_t)(row * ASTR + colA) * 2);
            }
            int rowB = kstep * 16 + (lg & 1) * 8 + lrow;
#pragma unroll
            for (int np = 0; np < 2; np++) {
                uint32_t t[4];
                int colB = wn * 32 + np * 16 + (lg >> 1) * 8;
                ldsm4t(t, bbase + (uint32_t)(rowB * BSTR + colB) * 2);
                bf[np * 2][0] = t[0]; bf[np * 2][1] = t[1];
                bf[np * 2 + 1][0] = t[2]; bf[np * 2 + 1][1] = t[3];
            }
#pragma unroll
            for (int mi = 0; mi < 4; mi++)
#pragma unroll
                for (int ni = 0; ni < 4; ni++) mma16(acc[mi][ni], af[mi], bf[ni]);
        }
    }

    // ---- C writeback ----
#pragma unroll
    for (int mi = 0; mi < 4; mi++) {
        int r0 = m0 + wm * 64 + mi * 16 + gid;
#pragma unroll
        for (int ni = 0; ni < 4; ni++) {
            int c0 = n0 + wn * 32 + ni * 8 + tg * 2;
            if (OUT_HALF) {
                __half* C = (__half*)Cv;
                if (r0 < M && c0 < N) {
                    half2 h = __floats2half2_rn(acc[mi][ni][0], acc[mi][ni][1]);
                    *(half2*)(C + (size_t)r0 * N + c0) = h;
                }
                if (r0 + 8 < M && c0 < N) {
                    half2 h = __floats2half2_rn(acc[mi][ni][2], acc[mi][ni][3]);
                    *(half2*)(C + (size_t)(r0 + 8) * N + c0) = h;
                }
            } else {
                float* C = (float*)Cv;
                if (r0 < M) {
                    if (c0 < N) C[(size_t)r0 * N + c0] = acc[mi][ni][0];
                    if (c0 + 1 < N) C[(size_t)r0 * N + c0 + 1] = acc[mi][ni][1];
                }
                if (r0 + 8 < M) {
                    if (c0 < N) C[(size_t)(r0 + 8) * N + c0] = acc[mi][ni][2];
                    if (c0 + 1 < N) C[(size_t)(r0 + 8) * N + c0 + 1] = acc[mi][ni][3];
                }
            }
        }
    }

    // ---- fused el/er projection (warp cols == one head; plain stores) ----
    if (DO_ELR) {
        int head = (n0 >> 5) + wn;
        float alv[8], arv[8];
#pragma unroll
        for (int ni = 0; ni < 4; ni++) {
            int c0 = n0 + wn * 32 + ni * 8 + tg * 2;
            alv[ni * 2] = __ldg(al + c0); alv[ni * 2 + 1] = __ldg(al + c0 + 1);
            arv[ni * 2] = __ldg(ar + c0); arv[ni * 2 + 1] = __ldg(ar + c0 + 1);
        }
#pragma unroll
        for (int mi = 0; mi < 4; mi++) {
            float el0 = 0.f, el1 = 0.f, er0 = 0.f, er1 = 0.f;
#pragma unroll
            for (int ni = 0; ni < 4; ni++) {
                el0 += acc[mi][ni][0] * alv[ni * 2] + acc[mi][ni][1] * alv[ni * 2 + 1];
                el1 += acc[mi][ni][2] * alv[ni * 2] + acc[mi][ni][3] * alv[ni * 2 + 1];
                er0 += acc[mi][ni][0] * arv[ni * 2] + acc[mi][ni][1] * arv[ni * 2 + 1];
                er1 += acc[mi][ni][2] * arv[ni * 2] + acc[mi][ni][3] * arv[ni * 2 + 1];
            }
            el0 += __shfl_xor_sync(0xffffffffu, el0, 1);
            el0 += __shfl_xor_sync(0xffffffffu, el0, 2);
            el1 += __shfl_xor_sync(0xffffffffu, el1, 1);
            el1 += __shfl_xor_sync(0xffffffffu, el1, 2);
            er0 += __shfl_xor_sync(0xffffffffu, er0, 1);
            er0 += __shfl_xor_sync(0xffffffffu, er0, 2);
            er1 += __shfl_xor_sync(0xffffffffu, er1, 1);
            er1 += __shfl_xor_sync(0xffffffffu, er1, 2);
            if (tg == 0) {
                int r0 = m0 + wm * 64 + mi * 16 + gid;
                if (r0 < M) { el[r0 * NH + head] = el0; er[r0 * NH + head] = er0; }
                if (r0 + 8 < M) { el[(r0 + 8) * NH + head] = el1; er[(r0 + 8) * NH + head] = er1; }
            }
        }
    }
}

__global__ void __launch_bounds__(256) k_mma_hh_elr(const __half* __restrict__ A,
                                                    const __half* __restrict__ B,
                                                    __half* __restrict__ C,
                                                    int M, int N, int K,
                                                    const float* __restrict__ al,
                                                    const float* __restrict__ ar,
                                                    float* __restrict__ el,
                                                    float* __restrict__ er) {
    mma_body<1, 1>(A, B, C, M, N, K, al, ar, el, er);
}
__global__ void __launch_bounds__(256) k_mma_hf(const __half* __restrict__ A,
                                                const __half* __restrict__ B,
                                                float* __restrict__ C,
                                                int M, int N, int K) {
    mma_body<0, 0>(A, B, C, M, N, K, nullptr, nullptr, nullptr, nullptr);
}

// ---------------- helpers ----------------
__device__ __forceinline__ float warp_sum(float v) {
#pragma unroll
    for (int o = 16; o > 0; o >>= 1) v += __shfl_xor_sync(0xffffffffu, v, o);
    return v;
}
__device__ __forceinline__ float leaky(float x) { return x > 0.f ? x : NEG_SLOPE * x; }

__global__ void k_elr1(const float* __restrict__ feat2, const float* __restrict__ al,
                       const float* __restrict__ ar, float* __restrict__ el,
                       float* __restrict__ er, int n) {
    int w = (blockIdx.x * blockDim.x + threadIdx.x) >> 5;
    int lane = threadIdx.x & 31;
    if (w >= n) return;
    const float* f = feat2 + (size_t)w * NCLS;
    float sl = f[lane] * __ldg(al + lane);
    float sr = f[lane] * __ldg(ar + lane);
    if (lane < 8) {
        sl += f[32 + lane] * __ldg(al + 32 + lane);
        sr += f[32 + lane] * __ldg(ar + 32 + lane);
    }
    sl = warp_sum(sl);
    sr = warp_sum(sr);
    if (lane == 0) { el[w] = sl; er[w] = sr; }
}

// ---------------- aggregation ----------------
__global__ void k_agg8(const __half* __restrict__ feath, const float* __restrict__ el,
                       const float* __restrict__ er, const int* __restrict__ rowptr,
                       const int* __restrict__ esrc, const float* __restrict__ bias,
                       __half* __restrict__ out, int n, int do_relu) {
    int node = (blockIdx.x * blockDim.x + threadIdx.x) >> 5;
    int lane = threadIdx.x & 31;
    if (node >= n) return;
    int beg = rowptr[node], end = rowptr[node + 1];
    int head = lane >> 2;
    int col = lane * 8;
    float ern = __ldg(er + node * NH + head);

    float acc[8];
#pragma unroll
    for (int r = 0; r < 8; r++) acc[r] = 0.f;
    float den = 0.f;

#pragma unroll 4
    for (int i = beg; i < end; i++) {
        int s = esrc[i];  // warp-uniform
        float w = __expf(leaky(__ldg(el + s * NH + head) + ern));
        den += w;
        uint4 pk = *((const uint4*)(feath + (size_t)s * HID + col));
        float2 f0 = __half22float2(u32_to_h2(pk.x));
        float2 f1 = __half22float2(u32_to_h2(pk.y));
        float2 f2 = __half22float2(u32_to_h2(pk.z));
        float2 f3 = __half22float2(u32_to_h2(pk.w));
        acc[0] = fmaf(w, f0.x, acc[0]); acc[1] = fmaf(w, f0.y, acc[1]);
        acc[2] = fmaf(w, f1.x, acc[2]); acc[3] = fmaf(w, f1.y, acc[3]);
        acc[4] = fmaf(w, f2.x, acc[4]); acc[5] = fmaf(w, f2.y, acc[5]);
        acc[6] = fmaf(w, f3.x, acc[6]); acc[7] = fmaf(w, f3.y, acc[7]);
    }
    float inv = 1.f / fmaxf(den, 1e-9f);
    float4 b0 = *(const float4*)(bias + col);
    float4 b1 = *(const float4*)(bias + col + 4);
    float ob[8] = {b0.x, b0.y, b0.z, b0.w, b1.x, b1.y, b1.z, b1.w};
    float o[8];
#pragma unroll
    for (int r = 0; r < 8; r++) {
        float v = fmaf(acc[r], inv, ob[r]);
        if (do_relu) v = fmaxf(v, 0.f);
        o[r] = v;
    }
    uint4 pk;
    pk.x = h2_to_u32(__floats2half2_rn(o[0], o[1]));
    pk.y = h2_to_u32(__floats2half2_rn(o[2], o[3]));
    pk.z = h2_to_u32(__floats2half2_rn(o[4], o[5]));
    pk.w = h2_to_u32(__floats2half2_rn(o[6], o[7]));
    *((uint4*)(out + (size_t)node * HID + col)) = pk;
}

__global__ void k_agg1(const float* __restrict__ feat2, const float* __restrict__ el,
                       const float* __restrict__ er, const int* __restrict__ rowptr,
                       const int* __restrict__ esrc, const float* __restrict__ bias,
                       float* __restrict__ out, int n) {
    int node = (blockIdx.x * blockDim.x + threadIdx.x) >> 5;
    int lane = threadIdx.x & 31;
    if (node >= n) return;
    int beg = rowptr[node], end = rowptr[node + 1];
    float ern = er[node];

    float4 acc = make_float4(0.f, 0.f, 0.f, 0.f);
    float den = 0.f;
#pragma unroll 4
    for (int i = beg; i < end; i++) {
        int s = esrc[i];
        float w = __expf(leaky(__ldg(el + s) + ern));
        den += w;
        if (lane < 10) {
            float4 f = *(const float4*)(feat2 + (size_t)s * NCLS + lane * 4);
            acc.x = fmaf(w, f.x, acc.x); acc.y = fmaf(w, f.y, acc.y);
            acc.z = fmaf(w, f.z, acc.z); acc.w = fmaf(w, f.w, acc.w);
        }
    }
    float inv = 1.f / fmaxf(den, 1e-9f);
    if (lane < 10) {
        float4 b = *(const float4*)(bias + lane * 4);
        float4 o;
        o.x = fmaf(acc.x, inv, b.x); o.y = fmaf(acc.y, inv, b.y);
        o.z = fmaf(acc.z, inv, b.z); o.w = fmaf(acc.w, inv, b.w);
        *(float4*)(out + (size_t)node * NCLS + lane * 4) = o;
    }
}

// ---------------- host ----------------
extern "C" void kernel_launch(void* const* d_in, const int* in_sizes, int n_in,
                              void* d_out, int out_size) {
    const float* in_feat = (const float*)d_in[0];
    const int*   src     = (const int*)d_in[1];
    const int*   dst     = (const int*)d_in[2];
    const float* W0  = (const float*)d_in[3];
    const float* al0 = (const float*)d_in[4];
    const float* ar0 = (const float*)d_in[5];
    const float* b0  = (const float*)d_in[6];
    const float* W1  = (const float*)d_in[7];
    const float* al1 = (const float*)d_in[8];
    const float* ar1 = (const float*)d_in[9];
    const float* b1  = (const float*)d_in[10];
    const float* W2  = (const float*)d_in[11];
    const float* al2 = (const float*)d_in[12];
    const float* ar2 = (const float*)d_in[13];
    const float* b2  = (const float*)d_in[14];
    float* out = (float*)d_out;

    int n = NN;
    int E = in_sizes[1];

    float *feat2, *el, *er, *el2, *er2;
    __half *feath, *hh, *a0h, *w0h, *w1h, *w2h;
    int *deg, *cur, *rp, *esrc;
    cudaGetSymbolAddress((void**)&feath, g_feath);
    cudaGetSymbolAddress((void**)&hh, g_hh);
    cudaGetSymbolAddress((void**)&feat2, g_feat2);
    cudaGetSymbolAddress((void**)&el, g_el);
    cudaGetSymbolAddress((void**)&er, g_er);
    cudaGetSymbolAddress((void**)&el2, g_el2);
    cudaGetSymbolAddress((void**)&er2, g_er2);
    cudaGetSymbolAddress((void**)&a0h, g_a0h);
    cudaGetSymbolAddress((void**)&w0h, g_w0h);
    cudaGetSymbolAddress((void**)&w1h, g_w1h);
    cudaGetSymbolAddress((void**)&w2h, g_w2h);
    cudaGetSymbolAddress((void**)&deg, g_deg);
    cudaGetSymbolAddress((void**)&cur, g_cursor);
    cudaGetSymbolAddress((void**)&rp, g_rowptr);
    cudaGetSymbolAddress((void**)&esrc, g_esrc);

    static cudaStream_t s1 = nullptr;
    static cudaEvent_t ev_fork = nullptr, ev_join = nullptr;
    static int attr_done = 0;
    if (!attr_done) {
        cudaFuncSetAttribute(k_mma_hh_elr, cudaFuncAttributeMaxDynamicSharedMemorySize,
                             SMEM_BYTES);
        cudaFuncSetAttribute(k_mma_hf, cudaFuncAttributeMaxDynamicSharedMemorySize,
                             SMEM_BYTES);
        cudaStreamCreateWithFlags(&s1, cudaStreamNonBlocking);
        cudaEventCreateWithFlags(&ev_fork, cudaEventDisableTiming);
        cudaEventCreateWithFlags(&ev_join, cudaEventDisableTiming);
        attr_done = 1;
    }

    // ---- fork: side stream builds CSR + converts W1/W2 (independent of s0 work)
    cudaEventRecord(ev_fork, 0);
    cudaStreamWaitEvent(s1, ev_fork, 0);

    k_zero<<<(n + 255) / 256, 256, 0, s1>>>(deg, n);
    k_hist<<<(E + 255) / 256, 256, 0, s1>>>(dst, deg, E);
    k_scan<<<1, 1024, 0, s1>>>(deg, rp, cur, n);
    k_scatter<<<(E + 255) / 256, 256, 0, s1>>>(dst, src, cur, esrc, E);
    k_cvth<<<(HID * HID / 8 + 255) / 256, 256, 0, s1>>>(w1h, W1, HID * HID / 8);
    k_cvth<<<(HID * NCLS / 8 + 255) / 256, 256, 0, s1>>>(w2h, W2, HID * NCLS / 8);
    cudaEventRecord(ev_join, s1);

    // ---- main stream: cvt inputs for layer-0, run GEMM0 (overlaps CSR build)
    k_cvth<<<(NN * INF_ / 8 + 255) / 256, 256>>>(a0h, in_feat, NN * INF_ / 8);
    k_cvth<<<(INF_ * HID / 8 + 255) / 256, 256>>>(w0h, W0, INF_ * HID / 8);

    int nwarp_blocks = (n + 7) / 8;

    // layer 0 (GEMM + fused el/er)
    {
        dim3 g((n + BM - 1) / BM, (HID + BN - 1) / BN);
        k_mma_hh_elr<<<g, 256, SMEM_BYTES>>>(a0h, w0h, feath, n, HID, INF_,
                                             al0, ar0, el, er);
        cudaStreamWaitEvent(0, ev_join, 0);  // need esrc/rowptr from here on
        k_agg8<<<nwarp_blocks, 256>>>(feath, el, er, rp, esrc, b0, hh, n, 1);
    }
    // layer 1
    {
        dim3 g((n + BM - 1) / BM, (HID + BN - 1) / BN);
        k_mma_hh_elr<<<g, 256, SMEM_BYTES>>>(hh, w1h, feath, n, HID, HID,
                                             al1, ar1, el, er);
        k_agg8<<<nwarp_blocks, 256>>>(feath, el, er, rp, esrc, b1, hh, n, 1);
    }
    // output layer (1 head, 40 classes)
    {
        dim3 g((n + BM - 1) / BM, (NCLS + BN - 1) / BN);
        k_mma_hf<<<g, 256, SMEM_BYTES>>>(hh, w2h, feat2, n, NCLS, HID);
        k_elr1<<<nwarp_blocks, 256>>>(feat2, al2, ar2, el2, er2, n);
        k_agg1<<<nwarp_blocks, 256>>>(feat2, el2, er2, rp, esrc, b2, out, n);
    }
}

// round 17
// speedup vs baseline: 1.2655x; 1.2655x over previous
#include <cuda_runtime.h>
#include <cuda_fp16.h>
#include <float.h>
#include <stdint.h>

// Problem constants (fixed shapes)
#define NN 50000
#define NE 800000
#define INF_ 512
#define HID 256
#define NH 8
#define HD 32
#define NCLS 40
#define NEG_SLOPE 0.2f

// ---------------- scratch (device globals; no allocs allowed) ----------------
__device__ __align__(16) __half g_feath[NN * HID];
__device__ __align__(16) __half g_hh[NN * HID];
__device__ __align__(16) float g_feat2[NN * NCLS];
__device__ __align__(16) float g_el[NN * NH];
__device__ __align__(16) float g_er[NN * NH];
__device__ __align__(16) float g_el2[NN];
__device__ __align__(16) float g_er2[NN];
__device__ __align__(16) __half g_a0h[NN * INF_];
__device__ __align__(16) __half g_w0h[INF_ * HID];
__device__ __align__(16) __half g_w1h[HID * HID];
__device__ __align__(16) __half g_w2h[HID * NCLS];
__device__ int g_deg[NN];
__device__ int g_cursor[NN];
__device__ int g_rowptr[NN + 1];
__device__ int g_esrc[NE];

// ---------------- bit casts ----------------
__device__ __forceinline__ uint32_t h2_to_u32(half2 h) {
    uint32_t u;
    memcpy(&u, &h, 4);
    return u;
}
__device__ __forceinline__ half2 u32_to_h2(uint32_t u) {
    half2 h;
    memcpy(&h, &u, 4);
    return h;
}

// ---------------- CSR build ----------------
__global__ void k_zero(int* p, int n) {
    int i = blockIdx.x * blockDim.x + threadIdx.x;
    if (i < n) p[i] = 0;
}

__global__ void k_hist(const int* __restrict__ dst, int* deg, int E) {
    int i = blockIdx.x * blockDim.x + threadIdx.x;
    if (i < E) atomicAdd(&deg[dst[i]], 1);
}

__global__ void k_scan(const int* __restrict__ deg, int* __restrict__ rowptr,
                       int* __restrict__ cursor, int n) {
    __shared__ int wsum[32];
    __shared__ int carry;
    int t = threadIdx.x, lane = t & 31, wid = t >> 5;
    if (t == 0) carry = 0;
    __syncthreads();
    for (int base = 0; base < n; base += blockDim.x) {
        int i = base + t;
        int v = (i < n) ? deg[i] : 0;
        int x = v;
#pragma unroll
        for (int o = 1; o < 32; o <<= 1) {
            int y = __shfl_up_sync(0xffffffffu, x, o);
            if (lane >= o) x += y;
        }
        if (lane == 31) wsum[wid] = x;
        __syncthreads();
        if (wid == 0) {
            int s = (lane < (int)(blockDim.x >> 5)) ? wsum[lane] : 0;
#pragma unroll
            for (int o = 1; o < 32; o <<= 1) {
                int y = __shfl_up_sync(0xffffffffu, s, o);
                if (lane >= o) s += y;
            }
            wsum[lane] = s;
        }
        __syncthreads();
        int woff = (wid == 0) ? 0 : wsum[wid - 1];
        int excl = carry + woff + x - v;
        if (i < n) { rowptr[i] = excl; cursor[i] = excl; }
        int total = wsum[(blockDim.x >> 5) - 1];
        __syncthreads();
        if (t == 0) carry += total;
        __syncthreads();
    }
    if (threadIdx.x == 0) rowptr[n] = carry;
}

__global__ void k_scatter(const int* __restrict__ dst, const int* __restrict__ src,
                          int* cursor, int* __restrict__ esrc, int E) {
    int i = blockIdx.x * blockDim.x + threadIdx.x;
    if (i < E) {
        int p = atomicAdd(&cursor[dst[i]], 1);
        esrc[p] = src[i];
    }
}

// ---------------- fused fp32 -> fp16 convert (all 4 arrays, one launch) ----------------
#define CVT0 (NN * INF_ / 8)
#define CVT1 (INF_ * HID / 8)
#define CVT2 (HID * HID / 8)
#define CVT3 (HID * NCLS / 8)
#define CVT_TOTAL (CVT0 + CVT1 + CVT2 + CVT3)

__device__ __forceinline__ void cvt8(__half* dst, const float* src, int i) {
    float4 v0 = ((const float4*)src)[i * 2];
    float4 v1 = ((const float4*)src)[i * 2 + 1];
    uint4 pk;
    pk.x = h2_to_u32(__floats2half2_rn(v0.x, v0.y));
    pk.y = h2_to_u32(__floats2half2_rn(v0.z, v0.w));
    pk.z = h2_to_u32(__floats2half2_rn(v1.x, v1.y));
    pk.w = h2_to_u32(__floats2half2_rn(v1.z, v1.w));
    ((uint4*)dst)[i] = pk;
}

__global__ void k_cvt_all(__half* __restrict__ a0h, const float* __restrict__ in_feat,
                          __half* __restrict__ w0h, const float* __restrict__ W0,
                          __half* __restrict__ w1h, const float* __restrict__ W1,
                          __half* __restrict__ w2h, const float* __restrict__ W2) {
    int i = blockIdx.x * blockDim.x + threadIdx.x;
    if (i < CVT0) { cvt8(a0h, in_feat, i); return; }
    i -= CVT0;
    if (i < CVT1) { cvt8(w0h, W0, i); return; }
    i -= CVT1;
    if (i < CVT2) { cvt8(w1h, W1, i); return; }
    i -= CVT2;
    if (i < CVT3) { cvt8(w2h, W2, i); }
}

// ---------------- FP16 tensor-core GEMM core ----------------
#define BM 128
#define BN 128
#define BK 32
#define NSTAGE 4
#define ASTR 40
#define BSTR 136
#define A_ST_H (BM * ASTR)
#define B_ST_H (BK * BSTR)
#define SMEM_BYTES (NSTAGE * (A_ST_H + B_ST_H) * 2)

__device__ __forceinline__ void ldsm4(uint32_t* r, uint32_t addr) {
    asm volatile("ldmatrix.sync.aligned.m8n8.x4.shared.b16 {%0,%1,%2,%3}, [%4];"
                 : "=r"(r[0]), "=r"(r[1]), "=r"(r[2]), "=r"(r[3]) : "r"(addr));
}
__device__ __forceinline__ void ldsm4t(uint32_t* r, uint32_t addr) {
    asm volatile("ldmatrix.sync.aligned.m8n8.x4.trans.shared.b16 {%0,%1,%2,%3}, [%4];"
                 : "=r"(r[0]), "=r"(r[1]), "=r"(r[2]), "=r"(r[3]) : "r"(addr));
}
__device__ __forceinline__ void mma16(float* c, const uint32_t* a, const uint32_t* b) {
    asm volatile(
        "mma.sync.aligned.m16n8k16.row.col.f32.f16.f16.f32 "
        "{%0,%1,%2,%3}, {%4,%5,%6,%7}, {%8,%9}, {%0,%1,%2,%3};"
        : "+f"(c[0]), "+f"(c[1]), "+f"(c[2]), "+f"(c[3])
        : "r"(a[0]), "r"(a[1]), "r"(a[2]), "r"(a[3]), "r"(b[0]), "r"(b[1]));
}
__device__ __forceinline__ void cp16(uint32_t dst, const void* src, bool pred) {
    int sz = pred ? 16 : 0;
    asm volatile("cp.async.cg.shared.global [%0], [%1], 16, %2;"
                 :: "r"(dst), "l"(src), "r"(sz));
}
__device__ __forceinline__ void cp_commit() {
    asm volatile("cp.async.commit_group;");
}
template <int N>
__device__ __forceinline__ void cp_wait() {
    asm volatile("cp.async.wait_group %0;" :: "n"(N));
}

template <int OUT_HALF, int DO_ELR>
__device__ __forceinline__ void mma_body(const __half* __restrict__ A,
                                         const __half* __restrict__ B,
                                         void* __restrict__ Cv,
                                         int M, int N, int K,
                                         const float* __restrict__ al,
                                         const float* __restrict__ ar,
                                         float* __restrict__ el,
                                         float* __restrict__ er) {
    extern __shared__ __half smemh[];
    uint32_t sbase;
    asm("{ .reg .u64 t; cvta.to.shared.u64 t, %1; cvt.u32.u64 %0, t; }"
        : "=r"(sbase) : "l"(smemh));

    int tid = threadIdx.x;
    int warp = tid >> 5, lane = tid & 31;
    int gid = lane >> 2, tg = lane & 3;
    int wm = warp >> 2, wn = warp & 3;
    int m0 = blockIdx.x * BM, n0 = blockIdx.y * BN;

    int ar_ = tid >> 2;
    int ac = (tid & 3) * 8;
    int bk = tid >> 4;
    int bn = (tid & 15) * 8;
    bool bok = (n0 + bn + 8 <= N);

    float acc[4][4][4];
#pragma unroll
    for (int mi = 0; mi < 4; mi++)
#pragma unroll
        for (int ni = 0; ni < 4; ni++)
#pragma unroll
            for (int r = 0; r < 4; r++) acc[mi][ni][r] = 0.f;

    int kTiles = K / BK;

#define FILL_STAGE_H(s, kt)                                                            \
    do {                                                                               \
        int k0 = (kt) * BK;                                                            \
        uint32_t abase = sbase + (uint32_t)(s) * (A_ST_H * 2);                         \
        uint32_t bbase = sbase + (uint32_t)(NSTAGE * A_ST_H + (s) * B_ST_H) * 2;       \
        cp16(abase + (ar_ * ASTR + ac) * 2,                                            \
             A + (size_t)(m0 + ar_) * K + k0 + ac, m0 + ar_ < M);                      \
        cp16(abase + ((ar_ + 64) * ASTR + ac) * 2,                                     \
             A + (size_t)(m0 + ar_ + 64) * K + k0 + ac, m0 + ar_ + 64 < M);            \
        cp16(bbase + (bk * BSTR + bn) * 2,                                             \
             B + (size_t)(k0 + bk) * N + n0 + bn, bok);                                \
        cp16(bbase + ((bk + 16) * BSTR + bn) * 2,                                      \
             B + (size_t)(k0 + bk + 16) * N + n0 + bn, bok);                           \
    } while (0)

#pragma unroll
    for (int s = 0; s < NSTAGE - 1; s++) {
        if (s < kTiles) FILL_STAGE_H(s, s);
        cp_commit();
    }

    int lrow = lane & 7, lg = lane >> 3;

    for (int kt = 0; kt < kTiles; kt++) {
        cp_wait<NSTAGE - 2>();
        __syncthreads();

        int nkt = kt + NSTAGE - 1;
        if (nkt < kTiles) FILL_STAGE_H(nkt % NSTAGE, nkt);
        cp_commit();

        int buf = kt % NSTAGE;
        uint32_t abase = sbase + (uint32_t)buf * (A_ST_H * 2);
        uint32_t bbase = sbase + (uint32_t)(NSTAGE * A_ST_H + buf * B_ST_H) * 2;

#pragma unroll
        for (int kstep = 0; kstep < 2; kstep++) {
            uint32_t af[4][4], bf[4][2];
            int colA = kstep * 16 + (lg >> 1) * 8;
#pragma unroll
            for (int mi = 0; mi < 4; mi++) {
                int row = wm * 64 + mi * 16 + (lg & 1) * 8 + lrow;
                ldsm4(af[mi], abase + (uint32_t)(row * ASTR + colA) * 2);
            }
            int rowB = kstep * 16 + (lg & 1) * 8 + lrow;
#pragma unroll
            for (int np = 0; np < 2; np++) {
                uint32_t t[4];
                int colB = wn * 32 + np * 16 + (lg >> 1) * 8;
                ldsm4t(t, bbase + (uint32_t)(rowB * BSTR + colB) * 2);
                bf[np * 2][0] = t[0]; bf[np * 2][1] = t[1];
                bf[np * 2 + 1][0] = t[2]; bf[np * 2 + 1][1] = t[3];
            }
#pragma unroll
            for (int mi = 0; mi < 4; mi++)
#pragma unroll
                for (int ni = 0; ni < 4; ni++) mma16(acc[mi][ni], af[mi], bf[ni]);
        }
    }

    // ---- C writeback ----
#pragma unroll
    for (int mi = 0; mi < 4; mi++) {
        int r0 = m0 + wm * 64 + mi * 16 + gid;
#pragma unroll
        for (int ni = 0; ni < 4; ni++) {
            int c0 = n0 + wn * 32 + ni * 8 + tg * 2;
            if (OUT_HALF) {
                __half* C = (__half*)Cv;
                if (r0 < M && c0 < N) {
                    half2 h = __floats2half2_rn(acc[mi][ni][0], acc[mi][ni][1]);
                    *(half2*)(C + (size_t)r0 * N + c0) = h;
                }
                if (r0 + 8 < M && c0 < N) {
                    half2 h = __floats2half2_rn(acc[mi][ni][2], acc[mi][ni][3]);
                    *(half2*)(C + (size_t)(r0 + 8) * N + c0) = h;
                }
            } else {
                float* C = (float*)Cv;
                if (r0 < M) {
                    if (c0 < N) C[(size_t)r0 * N + c0] = acc[mi][ni][0];
                    if (c0 + 1 < N) C[(size_t)r0 * N + c0 + 1] = acc[mi][ni][1];
                }
                if (r0 + 8 < M) {
                    if (c0 < N) C[(size_t)(r0 + 8) * N + c0] = acc[mi][ni][2];
                    if (c0 + 1 < N) C[(size_t)(r0 + 8) * N + c0 + 1] = acc[mi][ni][3];
                }
            }
        }
    }

    // ---- fused el/er projection (warp cols == one head; plain stores) ----
    if (DO_ELR) {
        int head = (n0 >> 5) + wn;
        float alv[8], arv[8];
#pragma unroll
        for (int ni = 0; ni < 4; ni++) {
            int c0 = n0 + wn * 32 + ni * 8 + tg * 2;
            alv[ni * 2] = __ldg(al + c0); alv[ni * 2 + 1] = __ldg(al + c0 + 1);
            arv[ni * 2] = __ldg(ar + c0); arv[ni * 2 + 1] = __ldg(ar + c0 + 1);
        }
#pragma unroll
        for (int mi = 0; mi < 4; mi++) {
            float el0 = 0.f, el1 = 0.f, er0 = 0.f, er1 = 0.f;
#pragma unroll
            for (int ni = 0; ni < 4; ni++) {
                el0 += acc[mi][ni][0] * alv[ni * 2] + acc[mi][ni][1] * alv[ni * 2 + 1];
                el1 += acc[mi][ni][2] * alv[ni * 2] + acc[mi][ni][3] * alv[ni * 2 + 1];
                er0 += acc[mi][ni][0] * arv[ni * 2] + acc[mi][ni][1] * arv[ni * 2 + 1];
                er1 += acc[mi][ni][2] * arv[ni * 2] + acc[mi][ni][3] * arv[ni * 2 + 1];
            }
            el0 += __shfl_xor_sync(0xffffffffu, el0, 1);
            el0 += __shfl_xor_sync(0xffffffffu, el0, 2);
            el1 += __shfl_xor_sync(0xffffffffu, el1, 1);
            el1 += __shfl_xor_sync(0xffffffffu, el1, 2);
            er0 += __shfl_xor_sync(0xffffffffu, er0, 1);
            er0 += __shfl_xor_sync(0xffffffffu, er0, 2);
            er1 += __shfl_xor_sync(0xffffffffu, er1, 1);
            er1 += __shfl_xor_sync(0xffffffffu, er1, 2);
            if (tg == 0) {
                int r0 = m0 + wm * 64 + mi * 16 + gid;
                if (r0 < M) { el[r0 * NH + head] = el0; er[r0 * NH + head] = er0; }
                if (r0 + 8 < M) { el[(r0 + 8) * NH + head] = el1; er[(r0 + 8) * NH + head] = er1; }
            }
        }
    }
}

__global__ void __launch_bounds__(256) k_mma_hh_elr(const __half* __restrict__ A,
                                                    const __half* __restrict__ B,
                                                    __half* __restrict__ C,
                                                    int M, int N, int K,
                                                    const float* __restrict__ al,
                                                    const float* __restrict__ ar,
                                                    float* __restrict__ el,
                                                    float* __restrict__ er) {
    mma_body<1, 1>(A, B, C, M, N, K, al, ar, el, er);
}
__global__ void __launch_bounds__(256) k_mma_hf(const __half* __restrict__ A,
                                                const __half* __restrict__ B,
                                                float* __restrict__ C,
                                                int M, int N, int K) {
    mma_body<0, 0>(A, B, C, M, N, K, nullptr, nullptr, nullptr, nullptr);
}

// ---------------- helpers ----------------
__device__ __forceinline__ float warp_sum(float v) {
#pragma unroll
    for (int o = 16; o > 0; o >>= 1) v += __shfl_xor_sync(0xffffffffu, v, o);
    return v;
}
__device__ __forceinline__ float leaky(float x) { return x > 0.f ? x : NEG_SLOPE * x; }

__global__ void k_elr1(const float* __restrict__ feat2, const float* __restrict__ al,
                       const float* __restrict__ ar, float* __restrict__ el,
                       float* __restrict__ er, int n) {
    int w = (blockIdx.x * blockDim.x + threadIdx.x) >> 5;
    int lane = threadIdx.x & 31;
    if (w >= n) return;
    const float* f = feat2 + (size_t)w * NCLS;
    float sl = f[lane] * __ldg(al + lane);
    float sr = f[lane] * __ldg(ar + lane);
    if (lane < 8) {
        sl += f[32 + lane] * __ldg(al + 32 + lane);
        sr += f[32 + lane] * __ldg(ar + 32 + lane);
    }
    sl = warp_sum(sl);
    sr = warp_sum(sr);
    if (lane == 0) { el[w] = sl; er[w] = sr; }
}

// ---------------- aggregation ----------------
__global__ void k_agg8(const __half* __restrict__ feath, const float* __restrict__ el,
                       const float* __restrict__ er, const int* __restrict__ rowptr,
                       const int* __restrict__ esrc, const float* __restrict__ bias,
                       __half* __restrict__ out, int n, int do_relu) {
    int node = (blockIdx.x * blockDim.x + threadIdx.x) >> 5;
    int lane = threadIdx.x & 31;
    if (node >= n) return;
    int beg = rowptr[node], end = rowptr[node + 1];
    int head = lane >> 2;
    int col = lane * 8;
    float ern = __ldg(er + node * NH + head);

    float acc[8];
#pragma unroll
    for (int r = 0; r < 8; r++) acc[r] = 0.f;
    float den = 0.f;

#pragma unroll 4
    for (int i = beg; i < end; i++) {
        int s = esrc[i];  // warp-uniform
        float w = __expf(leaky(__ldg(el + s * NH + head) + ern));
        den += w;
        uint4 pk = *((const uint4*)(feath + (size_t)s * HID + col));
        float2 f0 = __half22float2(u32_to_h2(pk.x));
        float2 f1 = __half22float2(u32_to_h2(pk.y));
        float2 f2 = __half22float2(u32_to_h2(pk.z));
        float2 f3 = __half22float2(u32_to_h2(pk.w));
        acc[0] = fmaf(w, f0.x, acc[0]); acc[1] = fmaf(w, f0.y, acc[1]);
        acc[2] = fmaf(w, f1.x, acc[2]); acc[3] = fmaf(w, f1.y, acc[3]);
        acc[4] = fmaf(w, f2.x, acc[4]); acc[5] = fmaf(w, f2.y, acc[5]);
        acc[6] = fmaf(w, f3.x, acc[6]); acc[7] = fmaf(w, f3.y, acc[7]);
    }
    float inv = 1.f / fmaxf(den, 1e-9f);
    float4 b0 = *(const float4*)(bias + col);
    float4 b1 = *(const float4*)(bias + col + 4);
    float ob[8] = {b0.x, b0.y, b0.z, b0.w, b1.x, b1.y, b1.z, b1.w};
    float o[8];
#pragma unroll
    for (int r = 0; r < 8; r++) {
        float v = fmaf(acc[r], inv, ob[r]);
        if (do_relu) v = fmaxf(v, 0.f);
        o[r] = v;
    }
    uint4 pk;
    pk.x = h2_to_u32(__floats2half2_rn(o[0], o[1]));
    pk.y = h2_to_u32(__floats2half2_rn(o[2], o[3]));
    pk.z = h2_to_u32(__floats2half2_rn(o[4], o[5]));
    pk.w = h2_to_u32(__floats2half2_rn(o[6], o[7]));
    *((uint4*)(out + (size_t)node * HID + col)) = pk;
}

__global__ void k_agg1(const float* __restrict__ feat2, const float* __restrict__ el,
                       const float* __restrict__ er, const int* __restrict__ rowptr,
                       const int* __restrict__ esrc, const float* __restrict__ bias,
                       float* __restrict__ out, int n) {
    int node = (blockIdx.x * blockDim.x + threadIdx.x) >> 5;
    int lane = threadIdx.x & 31;
    if (node >= n) return;
    int beg = rowptr[node], end = rowptr[node + 1];
    float ern = er[node];

    float4 acc = make_float4(0.f, 0.f, 0.f, 0.f);
    float den = 0.f;
#pragma unroll 4
    for (int i = beg; i < end; i++) {
        int s = esrc[i];
        float w = __expf(leaky(__ldg(el + s) + ern));
        den += w;
        if (lane < 10) {
            float4 f = *(const float4*)(feat2 + (size_t)s * NCLS + lane * 4);
            acc.x = fmaf(w, f.x, acc.x); acc.y = fmaf(w, f.y, acc.y);
            acc.z = fmaf(w, f.z, acc.z); acc.w = fmaf(w, f.w, acc.w);
        }
    }
    float inv = 1.f / fmaxf(den, 1e-9f);
    if (lane < 10) {
        float4 b = *(const float4*)(bias + lane * 4);
        float4 o;
        o.x = fmaf(acc.x, inv, b.x); o.y = fmaf(acc.y, inv, b.y);
        o.z = fmaf(acc.z, inv, b.z); o.w = fmaf(acc.w, inv, b.w);
        *(float4*)(out + (size_t)node * NCLS + lane * 4) = o;
    }
}

// ---------------- host ----------------
extern "C" void kernel_launch(void* const* d_in, const int* in_sizes, int n_in,
                              void* d_out, int out_size) {
    const float* in_feat = (const float*)d_in[0];
    const int*   src     = (const int*)d_in[1];
    const int*   dst     = (const int*)d_in[2];
    const float* W0  = (const float*)d_in[3];
    const float* al0 = (const float*)d_in[4];
    const float* ar0 = (const float*)d_in[5];
    const float* b0  = (const float*)d_in[6];
    const float* W1  = (const float*)d_in[7];
    const float* al1 = (const float*)d_in[8];
    const float* ar1 = (const float*)d_in[9];
    const float* b1  = (const float*)d_in[10];
    const float* W2  = (const float*)d_in[11];
    const float* al2 = (const float*)d_in[12];
    const float* ar2 = (const float*)d_in[13];
    const float* b2  = (const float*)d_in[14];
    float* out = (float*)d_out;

    int n = NN;
    int E = in_sizes[1];

    float *feat2, *el, *er, *el2, *er2;
    __half *feath, *hh, *a0h, *w0h, *w1h, *w2h;
    int *deg, *cur, *rp, *esrc;
    cudaGetSymbolAddress((void**)&feath, g_feath);
    cudaGetSymbolAddress((void**)&hh, g_hh);
    cudaGetSymbolAddress((void**)&feat2, g_feat2);
    cudaGetSymbolAddress((void**)&el, g_el);
    cudaGetSymbolAddress((void**)&er, g_er);
    cudaGetSymbolAddress((void**)&el2, g_el2);
    cudaGetSymbolAddress((void**)&er2, g_er2);
    cudaGetSymbolAddress((void**)&a0h, g_a0h);
    cudaGetSymbolAddress((void**)&w0h, g_w0h);
    cudaGetSymbolAddress((void**)&w1h, g_w1h);
    cudaGetSymbolAddress((void**)&w2h, g_w2h);
    cudaGetSymbolAddress((void**)&deg, g_deg);
    cudaGetSymbolAddress((void**)&cur, g_cursor);
    cudaGetSymbolAddress((void**)&rp, g_rowptr);
    cudaGetSymbolAddress((void**)&esrc, g_esrc);

    static int attr_done = 0;
    if (!attr_done) {
        cudaFuncSetAttribute(k_mma_hh_elr, cudaFuncAttributeMaxDynamicSharedMemorySize,
                             SMEM_BYTES);
        cudaFuncSetAttribute(k_mma_hf, cudaFuncAttributeMaxDynamicSharedMemorySize,
                             SMEM_BYTES);
        attr_done = 1;
    }

    // CSR by dst (single stream — fork experiment regressed, reverted)
    k_zero<<<(n + 255) / 256, 256>>>(deg, n);
    k_hist<<<(E + 255) / 256, 256>>>(dst, deg, E);
    k_scan<<<1, 1024>>>(deg, rp, cur, n);
    k_scatter<<<(E + 255) / 256, 256>>>(dst, src, cur, esrc, E);

    // all fp32->fp16 conversions in ONE launch
    k_cvt_all<<<(CVT_TOTAL + 255) / 256, 256>>>(a0h, in_feat, w0h, W0, w1h, W1, w2h, W2);

    int nwarp_blocks = (n + 7) / 8;

    // layer 0 (GEMM + fused el/er)
    {
        dim3 g((n + BM - 1) / BM, (HID + BN - 1) / BN);
        k_mma_hh_elr<<<g, 256, SMEM_BYTES>>>(a0h, w0h, feath, n, HID, INF_,
                                             al0, ar0, el, er);
        k_agg8<<<nwarp_blocks, 256>>>(feath, el, er, rp, esrc, b0, hh, n, 1);
    }
    // layer 1
    {
        dim3 g((n + BM - 1) / BM, (HID + BN - 1) / BN);
        k_mma_hh_elr<<<g, 256, SMEM_BYTES>>>(hh, w1h, feath, n, HID, HID,
                                             al1, ar1, el, er);
        k_agg8<<<nwarp_blocks, 256>>>(feath, el, er, rp, esrc, b1, hh, n, 1);
    }
    // output layer (1 head, 40 classes)
    {
        dim3 g((n + BM - 1) / BM, (NCLS + BN - 1) / BN);
        k_mma_hf<<<g, 256, SMEM_BYTES>>>(hh, w2h, feat2, n, NCLS, HID);
        k_elr1<<<nwarp_blocks, 256>>>(feat2, al2, ar2, el2, er2, n);
        k_agg1<<<nwarp_blocks, 256>>>(feat2, el2, er2, rp, esrc, b2, out, n);
    }
}